// round 10
// baseline (speedup 1.0000x reference)
#include <cuda_runtime.h>
#include <cuda_bf16.h>

// ---------------------------------------------------------------------------
// mLSTM block, GB300 sm_103a. Round 10:
//  - up/adj fused, f/i fused (proj N=5120), bcomb in prep (as round 9)
//  - GEMM rebuilt for ILP: 256 thr / 8 warps, warp tile 64x64 (2Mx4N),
//    double-buffered ldmatrix fragments (reg budget 256/thread),
//    CTA 128x256x64, 4-stage cp.async, XOR-swizzled SMEM.
// ---------------------------------------------------------------------------

#define NROWS 16384
#define SZB (16384ull * 1024ull)
#define M1  (1024ull * 1024ull)

__device__ __align__(16) __nv_bfloat16 g_act[10ull * SZB];
__device__ __align__(16) __nv_bfloat16 g_w[11ull * M1];
__device__ __align__(16) float g_bcat[5120];
__device__ __align__(16) float g_bcomb[1024];
__device__ __align__(16) float g_zero[1024];   // stays zero (never written)

__device__ __forceinline__ unsigned pack_bf2(float a, float b) {
    __nv_bfloat162 h = __floats2bfloat162_rn(a, b);
    return *reinterpret_cast<unsigned*>(&h);
}
__device__ __forceinline__ float4 ld_bf4(const __nv_bfloat16* p) {
    uint2 u = *reinterpret_cast<const uint2*>(p);
    __nv_bfloat162 a = *reinterpret_cast<__nv_bfloat162*>(&u.x);
    __nv_bfloat162 b = *reinterpret_cast<__nv_bfloat162*>(&u.y);
    float4 r;
    r.x = __bfloat162float(a.x); r.y = __bfloat162float(a.y);
    r.z = __bfloat162float(b.x); r.w = __bfloat162float(b.y);
    return r;
}
__device__ __forceinline__ void cpasync16(unsigned dst, const void* src) {
    asm volatile("cp.async.cg.shared.global [%0], [%1], 16;" :: "r"(dst), "l"(src));
}
__device__ __forceinline__ void ldsm_x4(unsigned& r0, unsigned& r1, unsigned& r2,
                                        unsigned& r3, unsigned a) {
    asm volatile("ldmatrix.sync.aligned.m8n8.x4.shared.b16 {%0,%1,%2,%3}, [%4];"
                 : "=r"(r0), "=r"(r1), "=r"(r2), "=r"(r3) : "r"(a));
}
__device__ __forceinline__ void ldsm_x4t(unsigned& r0, unsigned& r1, unsigned& r2,
                                         unsigned& r3, unsigned a) {
    asm volatile("ldmatrix.sync.aligned.m8n8.x4.trans.shared.b16 {%0,%1,%2,%3}, [%4];"
                 : "=r"(r0), "=r"(r1), "=r"(r2), "=r"(r3) : "r"(a));
}
__device__ __forceinline__ void mma_bf16(float* c, const unsigned* a, const unsigned* b) {
    asm volatile("mma.sync.aligned.m16n8k16.row.col.f32.bf16.bf16.f32 "
                 "{%0,%1,%2,%3}, {%4,%5,%6,%7}, {%8,%9}, {%0,%1,%2,%3};"
                 : "+f"(c[0]), "+f"(c[1]), "+f"(c[2]), "+f"(c[3])
                 : "r"(a[0]), "r"(a[1]), "r"(a[2]), "r"(a[3]), "r"(b[0]), "r"(b[1]));
}

// ---------------------------------------------------------------------------
// Single prep kernel (same as round 9).
// ---------------------------------------------------------------------------
#define R_A   524288
#define R_B   1048576
#define R_D   1310720
#define R_P   2621440
#define R_BI  2622720
#define R_BC  2623744

__global__ void prep_k(const float* __restrict__ W_up, const float* __restrict__ W_adj,
                       const float* __restrict__ W_down,
                       const float* __restrict__ Wq, const float* __restrict__ Wk,
                       const float* __restrict__ Wv, const float* __restrict__ Wi,
                       const float* __restrict__ Wf, const float* __restrict__ Wo,
                       const float* __restrict__ bq, const float* __restrict__ bk,
                       const float* __restrict__ bv, const float* __restrict__ bi,
                       const float* __restrict__ bf, const float* __restrict__ bo,
                       const float* __restrict__ b_up, const float* __restrict__ b_adj,
                       __nv_bfloat16* __restrict__ w, float* __restrict__ bcat,
                       float* __restrict__ bcomb) {
    int i = blockIdx.x * blockDim.x + threadIdx.x;
    if (i >= R_BC) return;
    if (i < R_D) {
        const float* src; __nv_bfloat16* dst; int off;
        if (i < R_A)      { src = W_up;   dst = w;          off = i; }
        else if (i < R_B) { src = W_adj;  dst = w + 2 * M1; off = i - R_A; }
        else              { src = W_down; dst = w + 9 * M1; off = i - R_B; }
        float4 v = reinterpret_cast<const float4*>(src)[off];
        uint2 u;
        u.x = pack_bf2(v.x, v.y); u.y = pack_bf2(v.z, v.w);
        reinterpret_cast<uint2*>(dst)[off] = u;
    } else if (i < R_P) {
        int li = i - R_D;
        int j = li >> 18, off = li & 262143;
        int k = off >> 8, c = off & 255;
        float4 v;
        if (j == 0)      v = reinterpret_cast<const float4*>(Wq)[off];
        else if (j == 1) {
            v = reinterpret_cast<const float4*>(Wk)[off];
            v.x *= 0.125f; v.y *= 0.125f; v.z *= 0.125f; v.w *= 0.125f;
        } else if (j == 2) v = reinterpret_cast<const float4*>(Wv)[off];
        else if (j == 3) {
            float4 a = reinterpret_cast<const float4*>(Wf)[off];
            float4 b = reinterpret_cast<const float4*>(Wi)[off];
            v.x = a.x - b.x; v.y = a.y - b.y; v.z = a.z - b.z; v.w = a.w - b.w;
        } else            v = reinterpret_cast<const float4*>(Wo)[off];
        uint2 u;
        u.x = pack_bf2(v.x, v.y); u.y = pack_bf2(v.z, v.w);
        *reinterpret_cast<uint2*>(w + 4 * M1 + (size_t)k * 5120 + (size_t)j * 1024 + c * 4) = u;
    } else if (i < R_BI) {
        int li = i - R_P;
        int j = li >> 8, off = li & 255;
        float4 v;
        if (j == 0)      v = reinterpret_cast<const float4*>(bq)[off];
        else if (j == 1) {
            v = reinterpret_cast<const float4*>(bk)[off];
            v.x *= 0.125f; v.y *= 0.125f; v.z *= 0.125f; v.w *= 0.125f;
        } else if (j == 2) v = reinterpret_cast<const float4*>(bv)[off];
        else if (j == 3) {
            float4 a = reinterpret_cast<const float4*>(bf)[off];
            float4 b = reinterpret_cast<const float4*>(bi)[off];
            v.x = a.x - b.x; v.y = a.y - b.y; v.z = a.z - b.z; v.w = a.w - b.w;
        } else            v = reinterpret_cast<const float4*>(bo)[off];
        reinterpret_cast<float4*>(bcat + (size_t)j * 1024)[off] = v;
    } else {
        int j = i - R_BI;
        float s = 0.f;
        for (int k = 0; k < 2048; k++) s += b_up[k] * W_adj[(size_t)k * 1024 + j];
        bcomb[j] = s + b_adj[j];
    }
}

// ---------------------------------------------------------------------------
// Block reduce (sum + sumsq) over 256 threads.
// ---------------------------------------------------------------------------
__device__ __forceinline__ void block_reduce2(float& s, float& ss, float* red) {
#pragma unroll
    for (int o = 16; o > 0; o >>= 1) {
        s  += __shfl_xor_sync(0xffffffffu, s,  o);
        ss += __shfl_xor_sync(0xffffffffu, ss, o);
    }
    int w = threadIdx.x >> 5;
    if ((threadIdx.x & 31) == 0) { red[w] = s; red[8 + w] = ss; }
    __syncthreads();
    s = 0.f; ss = 0.f;
#pragma unroll
    for (int i = 0; i < 8; i++) { s += red[i]; ss += red[8 + i]; }
}

// ---------------------------------------------------------------------------
// LN1: fp32 in, bf16 out. One block / row.
// ---------------------------------------------------------------------------
__global__ void ln_kernel(const float* __restrict__ x, const float* __restrict__ g,
                          const float* __restrict__ b, __nv_bfloat16* __restrict__ o) {
    __shared__ float red[16];
    int tid = threadIdx.x;
    size_t base = (size_t)blockIdx.x * 1024 + (size_t)tid * 4;
    float4 v = *reinterpret_cast<const float4*>(x + base);
    float s  = v.x + v.y + v.z + v.w;
    float ss = v.x*v.x + v.y*v.y + v.z*v.z + v.w*v.w;
    block_reduce2(s, ss, red);
    float mean = s * (1.f / 1024.f);
    float var  = ss * (1.f / 1024.f) - mean * mean;
    float rs = rsqrtf(var + 1e-3f);
    float4 gg = *reinterpret_cast<const float4*>(g + tid * 4);
    float4 bb = *reinterpret_cast<const float4*>(b + tid * 4);
    uint2 u;
    u.x = pack_bf2((v.x - mean) * rs * gg.x + bb.x, (v.y - mean) * rs * gg.y + bb.y);
    u.y = pack_bf2((v.z - mean) * rs * gg.z + bb.z, (v.w - mean) * rs * gg.w + bb.w);
    *reinterpret_cast<uint2*>(o + base) = u;
}

// ---------------------------------------------------------------------------
// Elementwise mLSTM + LN2 * sigmoid(adj). bf16 in/out. One block / row.
// proj rows 5120 wide: [q | k(scaled) | v | d=(f-i) | o].
// ---------------------------------------------------------------------------
__global__ void ew_kernel(const __nv_bfloat16* __restrict__ proj,
                          const __nv_bfloat16* __restrict__ adj,
                          const float* __restrict__ g2, const float* __restrict__ b2,
                          __nv_bfloat16* __restrict__ y) {
    __shared__ float red[16];
    int tid = threadIdx.x;
    size_t base5 = (size_t)blockIdx.x * 5120 + (size_t)tid * 4;
    size_t base  = (size_t)blockIdx.x * 1024 + (size_t)tid * 4;
    float4 q4 = ld_bf4(proj + base5);
    float4 k4 = ld_bf4(proj + base5 + 1024);
    float4 v4 = ld_bf4(proj + base5 + 2048);
    float4 d4 = ld_bf4(proj + base5 + 3072);
    float4 o4 = ld_bf4(proj + base5 + 4096);
    float qq[4] = {q4.x, q4.y, q4.z, q4.w};
    float kk[4] = {k4.x, k4.y, k4.z, k4.w};
    float vv[4] = {v4.x, v4.y, v4.z, v4.w};
    float dd[4] = {d4.x, d4.y, d4.z, d4.w};
    float oo[4] = {o4.x, o4.y, o4.z, o4.w};
    float h[4], s = 0.f, ss = 0.f;
#pragma unroll
    for (int e = 0; e < 4; e++) {
        float sig_o = 1.f / (1.f + __expf(-oo[e]));
        float fg = __expf(fminf(0.f, dd[e]));
        float u  = kk[e] * qq[e];
        float den = fmaxf(fabsf(u), 1.f);
        float hh = sig_o * fg * vv[e] * u / den;
        h[e] = hh; s += hh; ss += hh * hh;
    }
    block_reduce2(s, ss, red);
    float mean = s * (1.f / 1024.f);
    float var  = ss * (1.f / 1024.f) - mean * mean;
    float rs = rsqrtf(var + 1e-3f);
    float4 g4 = *reinterpret_cast<const float4*>(g2 + tid * 4);
    float4 bb4 = *reinterpret_cast<const float4*>(b2 + tid * 4);
    float4 a4 = ld_bf4(adj + base);
    float ga[4] = {g4.x, g4.y, g4.z, g4.w};
    float ba[4] = {bb4.x, bb4.y, bb4.z, bb4.w};
    float aa[4] = {a4.x, a4.y, a4.z, a4.w};
    float out[4];
#pragma unroll
    for (int e = 0; e < 4; e++) {
        float sig_a = 1.f / (1.f + __expf(-aa[e]));
        out[e] = ((h[e] - mean) * rs * ga[e] + ba[e]) * sig_a;
    }
    uint2 u;
    u.x = pack_bf2(out[0], out[1]); u.y = pack_bf2(out[2], out[3]);
    *reinterpret_cast<uint2*>(y + base) = u;
}

// ---------------------------------------------------------------------------
// bf16 GEMM: C = A[M,K] @ B[K,N] + bias; bf16 or fp32(+resid) out.
// CTA 128x256x64, 256 threads, 8 warps, warp tile 64x64 (2M x 4N warps).
// Double-buffered ldmatrix fragments (load kk+1 during kk MMAs).
// 4-stage cp.async, XOR swizzle (16B chunk ^ row&7), 1 barrier / k-chunk.
// M%128==0, N%256==0, K%64==0.
// ---------------------------------------------------------------------------
#define STG_B 49152u
#define GSMEM (4u * STG_B)

template<bool FP32OUT>
__global__ __launch_bounds__(256, 1) void gemm_bf16(
    const __nv_bfloat16* __restrict__ A, const __nv_bfloat16* __restrict__ Bw,
    const float* __restrict__ bias, const float* __restrict__ resid,
    void* __restrict__ Cv, int N, int K) {
    extern __shared__ char smc[];
    unsigned sbase = (unsigned)__cvta_generic_to_shared(smc);
    const int tid = threadIdx.x, lane = tid & 31, wid = tid >> 5;
    const int wm = wid & 1, wn = wid >> 1;          // 2 M-warps x 4 N-warps
    const int bm = blockIdx.y * 128, bn = blockIdx.x * 256;

    float acc[4][8][4];
#pragma unroll
    for (int mi = 0; mi < 4; mi++)
#pragma unroll
        for (int ni = 0; ni < 8; ni++)
#pragma unroll
            for (int e = 0; e < 4; e++) acc[mi][ni][e] = 0.f;

    const __nv_bfloat16* ag = A + (size_t)bm * K;
    const __nv_bfloat16* bg = Bw + bn;

    auto issue = [&](int s, int k0) {
        unsigned sa = sbase + (unsigned)s * STG_B;
        unsigned sb = sa + 16384u;
#pragma unroll
        for (int i = 0; i < 4; i++) {               // A: 128 rows x 8 chunks
            int idx = tid + i * 256;
            int r = idx >> 3, c = idx & 7;
            cpasync16(sa + r * 128 + ((c ^ (r & 7)) << 4),
                      ag + (size_t)r * K + k0 + c * 8);
        }
#pragma unroll
        for (int i = 0; i < 8; i++) {               // B: 64 rows x 32 chunks
            int idx = tid + i * 256;
            int r = idx >> 5, c = idx & 31;
            cpasync16(sb + r * 512 + ((c ^ (r & 7)) << 4),
                      bg + (size_t)(k0 + r) * N + c * 8);
        }
    };

    const int nk = K >> 6;
    issue(0, 0);
    asm volatile("cp.async.commit_group;" ::: "memory");
    issue(1, 64);
    asm volatile("cp.async.commit_group;" ::: "memory");
    issue(2, 128);
    asm volatile("cp.async.commit_group;" ::: "memory");

    const unsigned aoff = (unsigned)((wm * 64 + (lane & 15)) * 128);
    const unsigned asel = (lane >> 4) & 1;
    const unsigned axor = lane & 7;
    const unsigned boff = (unsigned)((((lane & 7) + ((lane >> 3) & 1) * 8)) * 512);
    const unsigned bsel = (lane >> 4) & 1;

    unsigned af[2][4][4], bf[2][8][2];
    auto lfrag = [&](int buf, unsigned sa, unsigned sb, int kk) {
#pragma unroll
        for (int mi = 0; mi < 4; mi++)
            ldsm_x4(af[buf][mi][0], af[buf][mi][1], af[buf][mi][2], af[buf][mi][3],
                    sa + aoff + mi * 2048 + ((((unsigned)(kk * 2) + asel) ^ axor) << 4));
#pragma unroll
        for (int n2 = 0; n2 < 4; n2++) {
            unsigned nch = (unsigned)(wn * 8 + n2 * 2) + bsel;
            ldsm_x4t(bf[buf][2 * n2][0], bf[buf][2 * n2][1],
                     bf[buf][2 * n2 + 1][0], bf[buf][2 * n2 + 1][1],
                     sb + kk * 8192 + boff + ((nch ^ axor) << 4));
        }
    };

    for (int kt = 0; kt < nk; kt++) {
        asm volatile("cp.async.wait_group 2;" ::: "memory");
        __syncthreads();
        if (kt + 3 < nk) issue((kt + 3) & 3, (kt + 3) << 6);
        asm volatile("cp.async.commit_group;" ::: "memory");

        unsigned sa = sbase + (unsigned)(kt & 3) * STG_B;
        unsigned sb = sa + 16384u;
        lfrag(0, sa, sb, 0);
#pragma unroll
        for (int kk = 0; kk < 4; kk++) {
            int cur = kk & 1;
            if (kk < 3) lfrag(cur ^ 1, sa, sb, kk + 1);
#pragma unroll
            for (int mi = 0; mi < 4; mi++)
#pragma unroll
                for (int ni = 0; ni < 8; ni++)
                    mma_bf16(acc[mi][ni], af[cur][mi], bf[cur][ni]);
        }
    }

    const int r0base = bm + wm * 64 + (lane >> 2);
    const int colbase = bn + wn * 64 + (lane & 3) * 2;
    if (!FP32OUT) {
        __nv_bfloat16* C = (__nv_bfloat16*)Cv;
#pragma unroll
        for (int mi = 0; mi < 4; mi++)
#pragma unroll
            for (int ni = 0; ni < 8; ni++) {
                int r0 = r0base + mi * 16, col = colbase + ni * 8;
                float2 bb = *reinterpret_cast<const float2*>(bias + col);
                *reinterpret_cast<unsigned*>(C + (size_t)r0 * N + col) =
                    pack_bf2(acc[mi][ni][0] + bb.x, acc[mi][ni][1] + bb.y);
                *reinterpret_cast<unsigned*>(C + (size_t)(r0 + 8) * N + col) =
                    pack_bf2(acc[mi][ni][2] + bb.x, acc[mi][ni][3] + bb.y);
            }
    } else {
        float* C = (float*)Cv;
#pragma unroll
        for (int mi = 0; mi < 4; mi++)
#pragma unroll
            for (int ni = 0; ni < 8; ni++) {
                int r0 = r0base + mi * 16, col = colbase + ni * 8;
                float2 bb = *reinterpret_cast<const float2*>(bias + col);
                float2 ra = *reinterpret_cast<const float2*>(resid + (size_t)r0 * N + col);
                float2 rb = *reinterpret_cast<const float2*>(resid + (size_t)(r0 + 8) * N + col);
                float2 v0, v1;
                v0.x = acc[mi][ni][0] + bb.x + ra.x;
                v0.y = acc[mi][ni][1] + bb.y + ra.y;
                v1.x = acc[mi][ni][2] + bb.x + rb.x;
                v1.y = acc[mi][ni][3] + bb.y + rb.y;
                *reinterpret_cast<float2*>(C + (size_t)r0 * N + col) = v0;
                *reinterpret_cast<float2*>(C + (size_t)(r0 + 8) * N + col) = v1;
            }
    }
}

// ---------------------------------------------------------------------------
// Launch. Order: prep(1), wcomb(2), ln(3), adj(4)<-profile target, proj(5),
// ew(6), down(7).
// ---------------------------------------------------------------------------
extern "C" void kernel_launch(void* const* d_in, const int* in_sizes, int n_in,
                              void* d_out, int out_size) {
    const float* x      = (const float*)d_in[0];
    const float* ln1g   = (const float*)d_in[1];
    const float* ln1b   = (const float*)d_in[2];
    const float* W_up   = (const float*)d_in[3];
    const float* b_up   = (const float*)d_in[4];
    const float* W_adj  = (const float*)d_in[5];
    const float* b_adj  = (const float*)d_in[6];
    const float* W_q = (const float*)d_in[7];   const float* b_q = (const float*)d_in[8];
    const float* W_k = (const float*)d_in[9];   const float* b_k = (const float*)d_in[10];
    const float* W_v = (const float*)d_in[11];  const float* b_v = (const float*)d_in[12];
    const float* W_i = (const float*)d_in[13];  const float* b_i = (const float*)d_in[14];
    const float* W_f = (const float*)d_in[15];  const float* b_f = (const float*)d_in[16];
    const float* W_o = (const float*)d_in[17];  const float* b_o = (const float*)d_in[18];
    const float* ln2g   = (const float*)d_in[19];
    const float* ln2b   = (const float*)d_in[20];
    const float* W_down = (const float*)d_in[21];
    const float* b_down = (const float*)d_in[22];
    float* out = (float*)d_out;

    void* p;
    cudaGetSymbolAddress(&p, g_act); __nv_bfloat16* act = (__nv_bfloat16*)p;
    cudaGetSymbolAddress(&p, g_w);   __nv_bfloat16* w   = (__nv_bfloat16*)p;
    cudaGetSymbolAddress(&p, g_bcat);  float* bcat  = (float*)p;
    cudaGetSymbolAddress(&p, g_bcomb); float* bcomb = (float*)p;
    cudaGetSymbolAddress(&p, g_zero);  float* bzero = (float*)p;

    __nv_bfloat16* xn   = act;                // reused as y after adj-GEMM
    __nv_bfloat16* adj  = act + 3 * SZB;
    __nv_bfloat16* proj = act + 4 * SZB;      // [N, 5120]
    __nv_bfloat16* y    = xn;

    __nv_bfloat16* w_up   = w;                // [1024,2048]
    __nv_bfloat16* w_adj  = w + 2 * M1;       // [2048,1024]
    __nv_bfloat16* w_cat  = w + 4 * M1;       // [1024,5120]
    __nv_bfloat16* w_down = w + 9 * M1;       // [1024,1024]
    __nv_bfloat16* w_comb = w + 10 * M1;      // [1024,1024]

    cudaFuncSetAttribute((const void*)gemm_bf16<false>,
                         cudaFuncAttributeMaxDynamicSharedMemorySize, GSMEM);
    cudaFuncSetAttribute((const void*)gemm_bf16<true>,
                         cudaFuncAttributeMaxDynamicSharedMemorySize, GSMEM);

    // 1) all weight prep (incl. bcomb) in one launch
    prep_k<<<(R_BC + 255) / 256, 256>>>(W_up, W_adj, W_down,
                                        W_q, W_k, W_v, W_i, W_f, W_o,
                                        b_q, b_k, b_v, b_i, b_f, b_o,
                                        b_up, b_adj, w, bcat, bcomb);
    // 2) W_comb = W_up @ W_adj  [1024,2048]@[2048,1024] (bias 0)
    gemm_bf16<false><<<dim3(4, 8), 256, GSMEM>>>(w_up, w_adj, bzero, nullptr,
                                                 w_comb, 1024, 2048);
    // 3) LN1
    ln_kernel<<<NROWS, 256>>>(x, ln1g, ln1b, xn);
    // 4) adj = xn @ W_comb + b_comb   [N,1024]@[1024,1024]   <- ncu target
    gemm_bf16<false><<<dim3(4, 128), 256, GSMEM>>>(xn, w_comb, bcomb, nullptr,
                                                   adj, 1024, 1024);
    // 5) proj = adj @ W_cat + b_cat   [N,1024]@[1024,5120]
    gemm_bf16<false><<<dim3(20, 128), 256, GSMEM>>>(adj, w_cat, bcat, nullptr,
                                                    proj, 5120, 1024);
    // 6) gates + LN2*sigmoid(adj)
    ew_kernel<<<NROWS, 256>>>(proj, adj, ln2g, ln2b, y);
    // 7) out = y @ W_down + b_down + x  (fp32)
    gemm_bf16<true><<<dim3(4, 128), 256, GSMEM>>>(y, w_down, b_down, x, out, 1024, 1024);
}

// round 11
// speedup vs baseline: 1.0770x; 1.0770x over previous
#include <cuda_runtime.h>
#include <cuda_bf16.h>

// ---------------------------------------------------------------------------
// mLSTM block, GB300 sm_103a. Round 11:
//  - pipeline as round 9 (up/adj fused, f/i fused proj N=5120, prep+bcomb)
//  - GEMM back to 2-CTA/SM config: CTA 128x128x64, 256 thr, warp 32x64
//    (4Mx2N), 3-stage cp.async (96KB -> occupancy 2), XOR-swizzled SMEM,
//    single barrier per k-chunk. Two CTAs/SM decouple barrier stalls.
// ---------------------------------------------------------------------------

#define NROWS 16384
#define SZB (16384ull * 1024ull)
#define M1  (1024ull * 1024ull)

__device__ __align__(16) __nv_bfloat16 g_act[10ull * SZB];
__device__ __align__(16) __nv_bfloat16 g_w[11ull * M1];
__device__ __align__(16) float g_bcat[5120];
__device__ __align__(16) float g_bcomb[1024];
__device__ __align__(16) float g_zero[1024];   // stays zero (never written)

__device__ __forceinline__ unsigned pack_bf2(float a, float b) {
    __nv_bfloat162 h = __floats2bfloat162_rn(a, b);
    return *reinterpret_cast<unsigned*>(&h);
}
__device__ __forceinline__ float4 ld_bf4(const __nv_bfloat16* p) {
    uint2 u = *reinterpret_cast<const uint2*>(p);
    __nv_bfloat162 a = *reinterpret_cast<__nv_bfloat162*>(&u.x);
    __nv_bfloat162 b = *reinterpret_cast<__nv_bfloat162*>(&u.y);
    float4 r;
    r.x = __bfloat162float(a.x); r.y = __bfloat162float(a.y);
    r.z = __bfloat162float(b.x); r.w = __bfloat162float(b.y);
    return r;
}
__device__ __forceinline__ void cpasync16(unsigned dst, const void* src) {
    asm volatile("cp.async.cg.shared.global [%0], [%1], 16;" :: "r"(dst), "l"(src));
}
__device__ __forceinline__ void ldsm_x4(unsigned& r0, unsigned& r1, unsigned& r2,
                                        unsigned& r3, unsigned a) {
    asm volatile("ldmatrix.sync.aligned.m8n8.x4.shared.b16 {%0,%1,%2,%3}, [%4];"
                 : "=r"(r0), "=r"(r1), "=r"(r2), "=r"(r3) : "r"(a));
}
__device__ __forceinline__ void ldsm_x4t(unsigned& r0, unsigned& r1, unsigned& r2,
                                         unsigned& r3, unsigned a) {
    asm volatile("ldmatrix.sync.aligned.m8n8.x4.trans.shared.b16 {%0,%1,%2,%3}, [%4];"
                 : "=r"(r0), "=r"(r1), "=r"(r2), "=r"(r3) : "r"(a));
}
__device__ __forceinline__ void mma_bf16(float* c, const unsigned* a, const unsigned* b) {
    asm volatile("mma.sync.aligned.m16n8k16.row.col.f32.bf16.bf16.f32 "
                 "{%0,%1,%2,%3}, {%4,%5,%6,%7}, {%8,%9}, {%0,%1,%2,%3};"
                 : "+f"(c[0]), "+f"(c[1]), "+f"(c[2]), "+f"(c[3])
                 : "r"(a[0]), "r"(a[1]), "r"(a[2]), "r"(a[3]), "r"(b[0]), "r"(b[1]));
}

// ---------------------------------------------------------------------------
// Single prep kernel (same as round 9).
// ---------------------------------------------------------------------------
#define R_A   524288
#define R_B   1048576
#define R_D   1310720
#define R_P   2621440
#define R_BI  2622720
#define R_BC  2623744

__global__ void prep_k(const float* __restrict__ W_up, const float* __restrict__ W_adj,
                       const float* __restrict__ W_down,
                       const float* __restrict__ Wq, const float* __restrict__ Wk,
                       const float* __restrict__ Wv, const float* __restrict__ Wi,
                       const float* __restrict__ Wf, const float* __restrict__ Wo,
                       const float* __restrict__ bq, const float* __restrict__ bk,
                       const float* __restrict__ bv, const float* __restrict__ bi,
                       const float* __restrict__ bf, const float* __restrict__ bo,
                       const float* __restrict__ b_up, const float* __restrict__ b_adj,
                       __nv_bfloat16* __restrict__ w, float* __restrict__ bcat,
                       float* __restrict__ bcomb) {
    int i = blockIdx.x * blockDim.x + threadIdx.x;
    if (i >= R_BC) return;
    if (i < R_D) {
        const float* src; __nv_bfloat16* dst; int off;
        if (i < R_A)      { src = W_up;   dst = w;          off = i; }
        else if (i < R_B) { src = W_adj;  dst = w + 2 * M1; off = i - R_A; }
        else              { src = W_down; dst = w + 9 * M1; off = i - R_B; }
        float4 v = reinterpret_cast<const float4*>(src)[off];
        uint2 u;
        u.x = pack_bf2(v.x, v.y); u.y = pack_bf2(v.z, v.w);
        reinterpret_cast<uint2*>(dst)[off] = u;
    } else if (i < R_P) {
        int li = i - R_D;
        int j = li >> 18, off = li & 262143;
        int k = off >> 8, c = off & 255;
        float4 v;
        if (j == 0)      v = reinterpret_cast<const float4*>(Wq)[off];
        else if (j == 1) {
            v = reinterpret_cast<const float4*>(Wk)[off];
            v.x *= 0.125f; v.y *= 0.125f; v.z *= 0.125f; v.w *= 0.125f;
        } else if (j == 2) v = reinterpret_cast<const float4*>(Wv)[off];
        else if (j == 3) {
            float4 a = reinterpret_cast<const float4*>(Wf)[off];
            float4 b = reinterpret_cast<const float4*>(Wi)[off];
            v.x = a.x - b.x; v.y = a.y - b.y; v.z = a.z - b.z; v.w = a.w - b.w;
        } else            v = reinterpret_cast<const float4*>(Wo)[off];
        uint2 u;
        u.x = pack_bf2(v.x, v.y); u.y = pack_bf2(v.z, v.w);
        *reinterpret_cast<uint2*>(w + 4 * M1 + (size_t)k * 5120 + (size_t)j * 1024 + c * 4) = u;
    } else if (i < R_BI) {
        int li = i - R_P;
        int j = li >> 8, off = li & 255;
        float4 v;
        if (j == 0)      v = reinterpret_cast<const float4*>(bq)[off];
        else if (j == 1) {
            v = reinterpret_cast<const float4*>(bk)[off];
            v.x *= 0.125f; v.y *= 0.125f; v.z *= 0.125f; v.w *= 0.125f;
        } else if (j == 2) v = reinterpret_cast<const float4*>(bv)[off];
        else if (j == 3) {
            float4 a = reinterpret_cast<const float4*>(bf)[off];
            float4 b = reinterpret_cast<const float4*>(bi)[off];
            v.x = a.x - b.x; v.y = a.y - b.y; v.z = a.z - b.z; v.w = a.w - b.w;
        } else            v = reinterpret_cast<const float4*>(bo)[off];
        reinterpret_cast<float4*>(bcat + (size_t)j * 1024)[off] = v;
    } else {
        int j = i - R_BI;
        float s = 0.f;
        for (int k = 0; k < 2048; k++) s += b_up[k] * W_adj[(size_t)k * 1024 + j];
        bcomb[j] = s + b_adj[j];
    }
}

// ---------------------------------------------------------------------------
// Block reduce (sum + sumsq) over 256 threads.
// ---------------------------------------------------------------------------
__device__ __forceinline__ void block_reduce2(float& s, float& ss, float* red) {
#pragma unroll
    for (int o = 16; o > 0; o >>= 1) {
        s  += __shfl_xor_sync(0xffffffffu, s,  o);
        ss += __shfl_xor_sync(0xffffffffu, ss, o);
    }
    int w = threadIdx.x >> 5;
    if ((threadIdx.x & 31) == 0) { red[w] = s; red[8 + w] = ss; }
    __syncthreads();
    s = 0.f; ss = 0.f;
#pragma unroll
    for (int i = 0; i < 8; i++) { s += red[i]; ss += red[8 + i]; }
}

// ---------------------------------------------------------------------------
// LN1: fp32 in, bf16 out. One block / row.
// ---------------------------------------------------------------------------
__global__ void ln_kernel(const float* __restrict__ x, const float* __restrict__ g,
                          const float* __restrict__ b, __nv_bfloat16* __restrict__ o) {
    __shared__ float red[16];
    int tid = threadIdx.x;
    size_t base = (size_t)blockIdx.x * 1024 + (size_t)tid * 4;
    float4 v = *reinterpret_cast<const float4*>(x + base);
    float s  = v.x + v.y + v.z + v.w;
    float ss = v.x*v.x + v.y*v.y + v.z*v.z + v.w*v.w;
    block_reduce2(s, ss, red);
    float mean = s * (1.f / 1024.f);
    float var  = ss * (1.f / 1024.f) - mean * mean;
    float rs = rsqrtf(var + 1e-3f);
    float4 gg = *reinterpret_cast<const float4*>(g + tid * 4);
    float4 bb = *reinterpret_cast<const float4*>(b + tid * 4);
    uint2 u;
    u.x = pack_bf2((v.x - mean) * rs * gg.x + bb.x, (v.y - mean) * rs * gg.y + bb.y);
    u.y = pack_bf2((v.z - mean) * rs * gg.z + bb.z, (v.w - mean) * rs * gg.w + bb.w);
    *reinterpret_cast<uint2*>(o + base) = u;
}

// ---------------------------------------------------------------------------
// Elementwise mLSTM + LN2 * sigmoid(adj). bf16 in/out. One block / row.
// proj rows 5120 wide: [q | k(scaled) | v | d=(f-i) | o].
// ---------------------------------------------------------------------------
__global__ void ew_kernel(const __nv_bfloat16* __restrict__ proj,
                          const __nv_bfloat16* __restrict__ adj,
                          const float* __restrict__ g2, const float* __restrict__ b2,
                          __nv_bfloat16* __restrict__ y) {
    __shared__ float red[16];
    int tid = threadIdx.x;
    size_t base5 = (size_t)blockIdx.x * 5120 + (size_t)tid * 4;
    size_t base  = (size_t)blockIdx.x * 1024 + (size_t)tid * 4;
    float4 q4 = ld_bf4(proj + base5);
    float4 k4 = ld_bf4(proj + base5 + 1024);
    float4 v4 = ld_bf4(proj + base5 + 2048);
    float4 d4 = ld_bf4(proj + base5 + 3072);
    float4 o4 = ld_bf4(proj + base5 + 4096);
    float qq[4] = {q4.x, q4.y, q4.z, q4.w};
    float kk[4] = {k4.x, k4.y, k4.z, k4.w};
    float vv[4] = {v4.x, v4.y, v4.z, v4.w};
    float dd[4] = {d4.x, d4.y, d4.z, d4.w};
    float oo[4] = {o4.x, o4.y, o4.z, o4.w};
    float h[4], s = 0.f, ss = 0.f;
#pragma unroll
    for (int e = 0; e < 4; e++) {
        float sig_o = 1.f / (1.f + __expf(-oo[e]));
        float fg = __expf(fminf(0.f, dd[e]));
        float u  = kk[e] * qq[e];
        float den = fmaxf(fabsf(u), 1.f);
        float hh = sig_o * fg * vv[e] * u / den;
        h[e] = hh; s += hh; ss += hh * hh;
    }
    block_reduce2(s, ss, red);
    float mean = s * (1.f / 1024.f);
    float var  = ss * (1.f / 1024.f) - mean * mean;
    float rs = rsqrtf(var + 1e-3f);
    float4 g4 = *reinterpret_cast<const float4*>(g2 + tid * 4);
    float4 bb4 = *reinterpret_cast<const float4*>(b2 + tid * 4);
    float4 a4 = ld_bf4(adj + base);
    float ga[4] = {g4.x, g4.y, g4.z, g4.w};
    float ba[4] = {bb4.x, bb4.y, bb4.z, bb4.w};
    float aa[4] = {a4.x, a4.y, a4.z, a4.w};
    float out[4];
#pragma unroll
    for (int e = 0; e < 4; e++) {
        float sig_a = 1.f / (1.f + __expf(-aa[e]));
        out[e] = ((h[e] - mean) * rs * ga[e] + ba[e]) * sig_a;
    }
    uint2 u;
    u.x = pack_bf2(out[0], out[1]); u.y = pack_bf2(out[2], out[3]);
    *reinterpret_cast<uint2*>(y + base) = u;
}

// ---------------------------------------------------------------------------
// bf16 GEMM: C = A[M,K] @ B[K,N] + bias; bf16 or fp32(+resid) out.
// CTA 128x128x64, 256 threads, warp tile 32x64 (4M x 2N warps),
// mma.m16n8k16, ldmatrix.x4, 3-stage cp.async (96KB -> 2 CTAs/SM),
// XOR swizzle (16B chunk ^ row&7), single barrier per k-chunk
// (iter kt's issue targets stage (kt-1)%3, whose readers passed this
// iteration's top barrier). M%128==0, N%128==0, K%64==0.
// ---------------------------------------------------------------------------
#define STG_B 32768u       // A 16KB + B 16KB
#define ASTG  16384u
#define GSMEM (3u * STG_B)

template<bool FP32OUT>
__global__ __launch_bounds__(256, 2) void gemm_bf16(
    const __nv_bfloat16* __restrict__ A, const __nv_bfloat16* __restrict__ Bw,
    const float* __restrict__ bias, const float* __restrict__ resid,
    void* __restrict__ Cv, int N, int K) {
    extern __shared__ char smc[];
    unsigned sbase = (unsigned)__cvta_generic_to_shared(smc);
    const int tid = threadIdx.x, lane = tid & 31, wid = tid >> 5;
    const int wm = wid & 3, wn = wid >> 2;          // 4 M-warps x 2 N-warps
    const int bm = blockIdx.y * 128, bn = blockIdx.x * 128;

    float acc[2][8][4];
#pragma unroll
    for (int mi = 0; mi < 2; mi++)
#pragma unroll
        for (int ni = 0; ni < 8; ni++)
#pragma unroll
            for (int e = 0; e < 4; e++) acc[mi][ni][e] = 0.f;

    const __nv_bfloat16* ag = A + (size_t)bm * K;
    const __nv_bfloat16* bg = Bw + bn;

    auto issue = [&](int s, int k0) {
        unsigned sa = sbase + (unsigned)s * STG_B;
        unsigned sb = sa + ASTG;
#pragma unroll
        for (int i = 0; i < 4; i++) {               // A: 128 rows x 8 chunks
            int idx = tid + i * 256;
            int r = idx >> 3, c = idx & 7;
            cpasync16(sa + r * 128 + ((c ^ (r & 7)) << 4),
                      ag + (size_t)r * K + k0 + c * 8);
        }
#pragma unroll
        for (int i = 0; i < 4; i++) {               // B: 64 rows x 16 chunks
            int idx = tid + i * 256;
            int r = idx >> 4, c = idx & 15;
            cpasync16(sb + r * 256 + ((c ^ (r & 7)) << 4),
                      bg + (size_t)(k0 + r) * N + c * 8);
        }
    };

    const int nk = K >> 6;
    issue(0, 0);
    asm volatile("cp.async.commit_group;" ::: "memory");
    issue(1, 64);
    asm volatile("cp.async.commit_group;" ::: "memory");

    const unsigned aoff = (unsigned)((wm * 32 + (lane & 15)) * 128);
    const unsigned asel = (lane >> 4) & 1;
    const unsigned axor = lane & 7;
    const unsigned boff = (unsigned)((((lane & 7) + ((lane >> 3) & 1) * 8)) * 256);
    const unsigned bsel = (lane >> 4) & 1;

    for (int kt = 0; kt < nk; kt++) {
        asm volatile("cp.async.wait_group 1;" ::: "memory");
        __syncthreads();
        if (kt + 2 < nk) issue((kt + 2) % 3, (kt + 2) << 6);
        asm volatile("cp.async.commit_group;" ::: "memory");

        unsigned sa = sbase + (unsigned)(kt % 3) * STG_B;
        unsigned sb = sa + ASTG;
#pragma unroll
        for (int kk = 0; kk < 4; kk++) {
            unsigned a[2][4];
#pragma unroll
            for (int mi = 0; mi < 2; mi++)
                ldsm_x4(a[mi][0], a[mi][1], a[mi][2], a[mi][3],
                        sa + aoff + mi * 2048 + ((((unsigned)(kk * 2) + asel) ^ axor) << 4));
            unsigned b[8][2];
#pragma unroll
            for (int n2 = 0; n2 < 4; n2++) {
                unsigned nch = (unsigned)(wn * 8 + n2 * 2) + bsel;
                ldsm_x4t(b[2 * n2][0], b[2 * n2][1], b[2 * n2 + 1][0], b[2 * n2 + 1][1],
                         sb + kk * 4096 + boff + ((nch ^ axor) << 4));
            }
#pragma unroll
            for (int mi = 0; mi < 2; mi++)
#pragma unroll
                for (int ni = 0; ni < 8; ni++)
                    mma_bf16(acc[mi][ni], a[mi], b[ni]);
        }
    }

    const int r0base = bm + wm * 32 + (lane >> 2);
    const int colbase = bn + wn * 64 + (lane & 3) * 2;
    if (!FP32OUT) {
        __nv_bfloat16* C = (__nv_bfloat16*)Cv;
#pragma unroll
        for (int mi = 0; mi < 2; mi++)
#pragma unroll
            for (int ni = 0; ni < 8; ni++) {
                int r0 = r0base + mi * 16, col = colbase + ni * 8;
                float2 bb = *reinterpret_cast<const float2*>(bias + col);
                *reinterpret_cast<unsigned*>(C + (size_t)r0 * N + col) =
                    pack_bf2(acc[mi][ni][0] + bb.x, acc[mi][ni][1] + bb.y);
                *reinterpret_cast<unsigned*>(C + (size_t)(r0 + 8) * N + col) =
                    pack_bf2(acc[mi][ni][2] + bb.x, acc[mi][ni][3] + bb.y);
            }
    } else {
        float* C = (float*)Cv;
#pragma unroll
        for (int mi = 0; mi < 2; mi++)
#pragma unroll
            for (int ni = 0; ni < 8; ni++) {
                int r0 = r0base + mi * 16, col = colbase + ni * 8;
                float2 bb = *reinterpret_cast<const float2*>(bias + col);
                float2 ra = *reinterpret_cast<const float2*>(resid + (size_t)r0 * N + col);
                float2 rb = *reinterpret_cast<const float2*>(resid + (size_t)(r0 + 8) * N + col);
                float2 v0, v1;
                v0.x = acc[mi][ni][0] + bb.x + ra.x;
                v0.y = acc[mi][ni][1] + bb.y + ra.y;
                v1.x = acc[mi][ni][2] + bb.x + rb.x;
                v1.y = acc[mi][ni][3] + bb.y + rb.y;
                *reinterpret_cast<float2*>(C + (size_t)r0 * N + col) = v0;
                *reinterpret_cast<float2*>(C + (size_t)(r0 + 8) * N + col) = v1;
            }
    }
}

// ---------------------------------------------------------------------------
// Launch. Order: prep(1), wcomb(2), ln(3), adj(4)<-profile target, proj(5),
// ew(6), down(7).
// ---------------------------------------------------------------------------
extern "C" void kernel_launch(void* const* d_in, const int* in_sizes, int n_in,
                              void* d_out, int out_size) {
    const float* x      = (const float*)d_in[0];
    const float* ln1g   = (const float*)d_in[1];
    const float* ln1b   = (const float*)d_in[2];
    const float* W_up   = (const float*)d_in[3];
    const float* b_up   = (const float*)d_in[4];
    const float* W_adj  = (const float*)d_in[5];
    const float* b_adj  = (const float*)d_in[6];
    const float* W_q = (const float*)d_in[7];   const float* b_q = (const float*)d_in[8];
    const float* W_k = (const float*)d_in[9];   const float* b_k = (const float*)d_in[10];
    const float* W_v = (const float*)d_in[11];  const float* b_v = (const float*)d_in[12];
    const float* W_i = (const float*)d_in[13];  const float* b_i = (const float*)d_in[14];
    const float* W_f = (const float*)d_in[15];  const float* b_f = (const float*)d_in[16];
    const float* W_o = (const float*)d_in[17];  const float* b_o = (const float*)d_in[18];
    const float* ln2g   = (const float*)d_in[19];
    const float* ln2b   = (const float*)d_in[20];
    const float* W_down = (const float*)d_in[21];
    const float* b_down = (const float*)d_in[22];
    float* out = (float*)d_out;

    void* p;
    cudaGetSymbolAddress(&p, g_act); __nv_bfloat16* act = (__nv_bfloat16*)p;
    cudaGetSymbolAddress(&p, g_w);   __nv_bfloat16* w   = (__nv_bfloat16*)p;
    cudaGetSymbolAddress(&p, g_bcat);  float* bcat  = (float*)p;
    cudaGetSymbolAddress(&p, g_bcomb); float* bcomb = (float*)p;
    cudaGetSymbolAddress(&p, g_zero);  float* bzero = (float*)p;

    __nv_bfloat16* xn   = act;                // reused as y after adj-GEMM
    __nv_bfloat16* adj  = act + 3 * SZB;
    __nv_bfloat16* proj = act + 4 * SZB;      // [N, 5120]
    __nv_bfloat16* y    = xn;

    __nv_bfloat16* w_up   = w;                // [1024,2048]
    __nv_bfloat16* w_adj  = w + 2 * M1;       // [2048,1024]
    __nv_bfloat16* w_cat  = w + 4 * M1;       // [1024,5120]
    __nv_bfloat16* w_down = w + 9 * M1;       // [1024,1024]
    __nv_bfloat16* w_comb = w + 10 * M1;      // [1024,1024]

    cudaFuncSetAttribute((const void*)gemm_bf16<false>,
                         cudaFuncAttributeMaxDynamicSharedMemorySize, GSMEM);
    cudaFuncSetAttribute((const void*)gemm_bf16<true>,
                         cudaFuncAttributeMaxDynamicSharedMemorySize, GSMEM);

    // 1) all weight prep (incl. bcomb) in one launch
    prep_k<<<(R_BC + 255) / 256, 256>>>(W_up, W_adj, W_down,
                                        W_q, W_k, W_v, W_i, W_f, W_o,
                                        b_q, b_k, b_v, b_i, b_f, b_o,
                                        b_up, b_adj, w, bcat, bcomb);
    // 2) W_comb = W_up @ W_adj  [1024,2048]@[2048,1024] (bias 0)
    gemm_bf16<false><<<dim3(8, 8), 256, GSMEM>>>(w_up, w_adj, bzero, nullptr,
                                                 w_comb, 1024, 2048);
    // 3) LN1
    ln_kernel<<<NROWS, 256>>>(x, ln1g, ln1b, xn);
    // 4) adj = xn @ W_comb + b_comb   [N,1024]@[1024,1024]   <- ncu target
    gemm_bf16<false><<<dim3(8, 128), 256, GSMEM>>>(xn, w_comb, bcomb, nullptr,
                                                   adj, 1024, 1024);
    // 5) proj = adj @ W_cat + b_cat   [N,1024]@[1024,5120]
    gemm_bf16<false><<<dim3(40, 128), 256, GSMEM>>>(adj, w_cat, bcat, nullptr,
                                                    proj, 5120, 1024);
    // 6) gates + LN2*sigmoid(adj)
    ew_kernel<<<NROWS, 256>>>(proj, adj, ln2g, ln2b, y);
    // 7) out = y @ W_down + b_down + x  (fp32)
    gemm_bf16<true><<<dim3(8, 128), 256, GSMEM>>>(y, w_down, b_down, x, out, 1024, 1024);
}

// round 12
// speedup vs baseline: 1.0847x; 1.0071x over previous
#include <cuda_runtime.h>
#include <cuda_bf16.h>

// ---------------------------------------------------------------------------
// mLSTM block, GB300 sm_103a. Round 12:
//  - pipeline as round 11 (up/adj fused, f/i fused proj N=5120, prep+bcomb)
//  - wcomb (W_up@W_adj) now split-K=8: 512 CTAs of K=256 each -> fp32
//    partials in a dead activation plane -> tiny reduce to bf16.
//    (was 64 CTAs / 0.22 waves, K-serial latency ~47us)
//  - GEMM core unchanged (frozen): CTA 128x128x64, 256 thr, warp 32x64,
//    3-stage cp.async, 2 CTAs/SM, XOR swizzle, 1 barrier/chunk.
//    MODE: 0 = bf16 out + bias, 1 = fp32 out + bias + resid, 2 = fp32 partial.
// ---------------------------------------------------------------------------

#define NROWS 16384
#define SZB (16384ull * 1024ull)
#define M1  (1024ull * 1024ull)

__device__ __align__(16) __nv_bfloat16 g_act[10ull * SZB];
__device__ __align__(16) __nv_bfloat16 g_w[11ull * M1];
__device__ __align__(16) float g_bcat[5120];
__device__ __align__(16) float g_bcomb[1024];

__device__ __forceinline__ unsigned pack_bf2(float a, float b) {
    __nv_bfloat162 h = __floats2bfloat162_rn(a, b);
    return *reinterpret_cast<unsigned*>(&h);
}
__device__ __forceinline__ float4 ld_bf4(const __nv_bfloat16* p) {
    uint2 u = *reinterpret_cast<const uint2*>(p);
    __nv_bfloat162 a = *reinterpret_cast<__nv_bfloat162*>(&u.x);
    __nv_bfloat162 b = *reinterpret_cast<__nv_bfloat162*>(&u.y);
    float4 r;
    r.x = __bfloat162float(a.x); r.y = __bfloat162float(a.y);
    r.z = __bfloat162float(b.x); r.w = __bfloat162float(b.y);
    return r;
}
__device__ __forceinline__ void cpasync16(unsigned dst, const void* src) {
    asm volatile("cp.async.cg.shared.global [%0], [%1], 16;" :: "r"(dst), "l"(src));
}
__device__ __forceinline__ void ldsm_x4(unsigned& r0, unsigned& r1, unsigned& r2,
                                        unsigned& r3, unsigned a) {
    asm volatile("ldmatrix.sync.aligned.m8n8.x4.shared.b16 {%0,%1,%2,%3}, [%4];"
                 : "=r"(r0), "=r"(r1), "=r"(r2), "=r"(r3) : "r"(a));
}
__device__ __forceinline__ void ldsm_x4t(unsigned& r0, unsigned& r1, unsigned& r2,
                                         unsigned& r3, unsigned a) {
    asm volatile("ldmatrix.sync.aligned.m8n8.x4.trans.shared.b16 {%0,%1,%2,%3}, [%4];"
                 : "=r"(r0), "=r"(r1), "=r"(r2), "=r"(r3) : "r"(a));
}
__device__ __forceinline__ void mma_bf16(float* c, const unsigned* a, const unsigned* b) {
    asm volatile("mma.sync.aligned.m16n8k16.row.col.f32.bf16.bf16.f32 "
                 "{%0,%1,%2,%3}, {%4,%5,%6,%7}, {%8,%9}, {%0,%1,%2,%3};"
                 : "+f"(c[0]), "+f"(c[1]), "+f"(c[2]), "+f"(c[3])
                 : "r"(a[0]), "r"(a[1]), "r"(a[2]), "r"(a[3]), "r"(b[0]), "r"(b[1]));
}

// ---------------------------------------------------------------------------
// Single prep kernel (same as round 9/11).
// ---------------------------------------------------------------------------
#define R_A   524288
#define R_B   1048576
#define R_D   1310720
#define R_P   2621440
#define R_BI  2622720
#define R_BC  2623744

__global__ void prep_k(const float* __restrict__ W_up, const float* __restrict__ W_adj,
                       const float* __restrict__ W_down,
                       const float* __restrict__ Wq, const float* __restrict__ Wk,
                       const float* __restrict__ Wv, const float* __restrict__ Wi,
                       const float* __restrict__ Wf, const float* __restrict__ Wo,
                       const float* __restrict__ bq, const float* __restrict__ bk,
                       const float* __restrict__ bv, const float* __restrict__ bi,
                       const float* __restrict__ bf, const float* __restrict__ bo,
                       const float* __restrict__ b_up, const float* __restrict__ b_adj,
                       __nv_bfloat16* __restrict__ w, float* __restrict__ bcat,
                       float* __restrict__ bcomb) {
    int i = blockIdx.x * blockDim.x + threadIdx.x;
    if (i >= R_BC) return;
    if (i < R_D) {
        const float* src; __nv_bfloat16* dst; int off;
        if (i < R_A)      { src = W_up;   dst = w;          off = i; }
        else if (i < R_B) { src = W_adj;  dst = w + 2 * M1; off = i - R_A; }
        else              { src = W_down; dst = w + 9 * M1; off = i - R_B; }
        float4 v = reinterpret_cast<const float4*>(src)[off];
        uint2 u;
        u.x = pack_bf2(v.x, v.y); u.y = pack_bf2(v.z, v.w);
        reinterpret_cast<uint2*>(dst)[off] = u;
    } else if (i < R_P) {
        int li = i - R_D;
        int j = li >> 18, off = li & 262143;
        int k = off >> 8, c = off & 255;
        float4 v;
        if (j == 0)      v = reinterpret_cast<const float4*>(Wq)[off];
        else if (j == 1) {
            v = reinterpret_cast<const float4*>(Wk)[off];
            v.x *= 0.125f; v.y *= 0.125f; v.z *= 0.125f; v.w *= 0.125f;
        } else if (j == 2) v = reinterpret_cast<const float4*>(Wv)[off];
        else if (j == 3) {
            float4 a = reinterpret_cast<const float4*>(Wf)[off];
            float4 b = reinterpret_cast<const float4*>(Wi)[off];
            v.x = a.x - b.x; v.y = a.y - b.y; v.z = a.z - b.z; v.w = a.w - b.w;
        } else            v = reinterpret_cast<const float4*>(Wo)[off];
        uint2 u;
        u.x = pack_bf2(v.x, v.y); u.y = pack_bf2(v.z, v.w);
        *reinterpret_cast<uint2*>(w + 4 * M1 + (size_t)k * 5120 + (size_t)j * 1024 + c * 4) = u;
    } else if (i < R_BI) {
        int li = i - R_P;
        int j = li >> 8, off = li & 255;
        float4 v;
        if (j == 0)      v = reinterpret_cast<const float4*>(bq)[off];
        else if (j == 1) {
            v = reinterpret_cast<const float4*>(bk)[off];
            v.x *= 0.125f; v.y *= 0.125f; v.z *= 0.125f; v.w *= 0.125f;
        } else if (j == 2) v = reinterpret_cast<const float4*>(bv)[off];
        else if (j == 3) {
            float4 a = reinterpret_cast<const float4*>(bf)[off];
            float4 b = reinterpret_cast<const float4*>(bi)[off];
            v.x = a.x - b.x; v.y = a.y - b.y; v.z = a.z - b.z; v.w = a.w - b.w;
        } else            v = reinterpret_cast<const float4*>(bo)[off];
        reinterpret_cast<float4*>(bcat + (size_t)j * 1024)[off] = v;
    } else {
        int j = i - R_BI;
        float s = 0.f;
        for (int k = 0; k < 2048; k++) s += b_up[k] * W_adj[(size_t)k * 1024 + j];
        bcomb[j] = s + b_adj[j];
    }
}

// Reduce 8 fp32 split-K partials [8 x 1M] -> bf16 [1M]. float4 granular.
__global__ void wred_k(const float* __restrict__ part, __nv_bfloat16* __restrict__ out) {
    int i = blockIdx.x * blockDim.x + threadIdx.x;     // 262144 float4 items
    if (i >= 262144) return;
    float4 s = reinterpret_cast<const float4*>(part)[i];
#pragma unroll
    for (int p = 1; p < 8; p++) {
        float4 v = reinterpret_cast<const float4*>(part + (size_t)p * M1)[i];
        s.x += v.x; s.y += v.y; s.z += v.z; s.w += v.w;
    }
    uint2 u;
    u.x = pack_bf2(s.x, s.y); u.y = pack_bf2(s.z, s.w);
    reinterpret_cast<uint2*>(out)[i] = u;
}

// ---------------------------------------------------------------------------
// Block reduce (sum + sumsq) over 256 threads.
// ---------------------------------------------------------------------------
__device__ __forceinline__ void block_reduce2(float& s, float& ss, float* red) {
#pragma unroll
    for (int o = 16; o > 0; o >>= 1) {
        s  += __shfl_xor_sync(0xffffffffu, s,  o);
        ss += __shfl_xor_sync(0xffffffffu, ss, o);
    }
    int w = threadIdx.x >> 5;
    if ((threadIdx.x & 31) == 0) { red[w] = s; red[8 + w] = ss; }
    __syncthreads();
    s = 0.f; ss = 0.f;
#pragma unroll
    for (int i = 0; i < 8; i++) { s += red[i]; ss += red[8 + i]; }
}

// ---------------------------------------------------------------------------
// LN1: fp32 in, bf16 out. One block / row.
// ---------------------------------------------------------------------------
__global__ void ln_kernel(const float* __restrict__ x, const float* __restrict__ g,
                          const float* __restrict__ b, __nv_bfloat16* __restrict__ o) {
    __shared__ float red[16];
    int tid = threadIdx.x;
    size_t base = (size_t)blockIdx.x * 1024 + (size_t)tid * 4;
    float4 v = *reinterpret_cast<const float4*>(x + base);
    float s  = v.x + v.y + v.z + v.w;
    float ss = v.x*v.x + v.y*v.y + v.z*v.z + v.w*v.w;
    block_reduce2(s, ss, red);
    float mean = s * (1.f / 1024.f);
    float var  = ss * (1.f / 1024.f) - mean * mean;
    float rs = rsqrtf(var + 1e-3f);
    float4 gg = *reinterpret_cast<const float4*>(g + tid * 4);
    float4 bb = *reinterpret_cast<const float4*>(b + tid * 4);
    uint2 u;
    u.x = pack_bf2((v.x - mean) * rs * gg.x + bb.x, (v.y - mean) * rs * gg.y + bb.y);
    u.y = pack_bf2((v.z - mean) * rs * gg.z + bb.z, (v.w - mean) * rs * gg.w + bb.w);
    *reinterpret_cast<uint2*>(o + base) = u;
}

// ---------------------------------------------------------------------------
// Elementwise mLSTM + LN2 * sigmoid(adj). bf16 in/out. One block / row.
// proj rows 5120 wide: [q | k(scaled) | v | d=(f-i) | o].
// ---------------------------------------------------------------------------
__global__ void ew_kernel(const __nv_bfloat16* __restrict__ proj,
                          const __nv_bfloat16* __restrict__ adj,
                          const float* __restrict__ g2, const float* __restrict__ b2,
                          __nv_bfloat16* __restrict__ y) {
    __shared__ float red[16];
    int tid = threadIdx.x;
    size_t base5 = (size_t)blockIdx.x * 5120 + (size_t)tid * 4;
    size_t base  = (size_t)blockIdx.x * 1024 + (size_t)tid * 4;
    float4 q4 = ld_bf4(proj + base5);
    float4 k4 = ld_bf4(proj + base5 + 1024);
    float4 v4 = ld_bf4(proj + base5 + 2048);
    float4 d4 = ld_bf4(proj + base5 + 3072);
    float4 o4 = ld_bf4(proj + base5 + 4096);
    float qq[4] = {q4.x, q4.y, q4.z, q4.w};
    float kk[4] = {k4.x, k4.y, k4.z, k4.w};
    float vv[4] = {v4.x, v4.y, v4.z, v4.w};
    float dd[4] = {d4.x, d4.y, d4.z, d4.w};
    float oo[4] = {o4.x, o4.y, o4.z, o4.w};
    float h[4], s = 0.f, ss = 0.f;
#pragma unroll
    for (int e = 0; e < 4; e++) {
        float sig_o = 1.f / (1.f + __expf(-oo[e]));
        float fg = __expf(fminf(0.f, dd[e]));
        float u  = kk[e] * qq[e];
        float den = fmaxf(fabsf(u), 1.f);
        float hh = sig_o * fg * vv[e] * u / den;
        h[e] = hh; s += hh; ss += hh * hh;
    }
    block_reduce2(s, ss, red);
    float mean = s * (1.f / 1024.f);
    float var  = ss * (1.f / 1024.f) - mean * mean;
    float rs = rsqrtf(var + 1e-3f);
    float4 g4 = *reinterpret_cast<const float4*>(g2 + tid * 4);
    float4 bb4 = *reinterpret_cast<const float4*>(b2 + tid * 4);
    float4 a4 = ld_bf4(adj + base);
    float ga[4] = {g4.x, g4.y, g4.z, g4.w};
    float ba[4] = {bb4.x, bb4.y, bb4.z, bb4.w};
    float aa[4] = {a4.x, a4.y, a4.z, a4.w};
    float out[4];
#pragma unroll
    for (int e = 0; e < 4; e++) {
        float sig_a = 1.f / (1.f + __expf(-aa[e]));
        out[e] = ((h[e] - mean) * rs * ga[e] + ba[e]) * sig_a;
    }
    uint2 u;
    u.x = pack_bf2(out[0], out[1]); u.y = pack_bf2(out[2], out[3]);
    *reinterpret_cast<uint2*>(y + base) = u;
}

// ---------------------------------------------------------------------------
// bf16 GEMM: C = A[M,Kld sliced] @ B[K,N] (+bias / +resid per MODE).
// MODE 0: bf16 out + bias.  MODE 1: fp32 out + bias + resid.
// MODE 2: fp32 partial (split-K over blockIdx.z; no bias).
// CTA 128x128x64, 256 threads, warp tile 32x64 (4M x 2N warps),
// 3-stage cp.async (96KB -> 2 CTAs/SM), XOR swizzle, 1 barrier / k-chunk.
// M%128==0, N%128==0, K%64==0.
// ---------------------------------------------------------------------------
#define STG_B 32768u       // A 16KB + B 16KB
#define ASTG  16384u
#define GSMEM (3u * STG_B)

template<int MODE>
__global__ __launch_bounds__(256, 2) void gemm_bf16(
    const __nv_bfloat16* __restrict__ A, const __nv_bfloat16* __restrict__ Bw,
    const float* __restrict__ bias, const float* __restrict__ resid,
    void* __restrict__ Cv, int N, int K, int Kld) {
    extern __shared__ char smc[];
    unsigned sbase = (unsigned)__cvta_generic_to_shared(smc);
    const int tid = threadIdx.x, lane = tid & 31, wid = tid >> 5;
    const int wm = wid & 3, wn = wid >> 2;          // 4 M-warps x 2 N-warps
    const int bm = blockIdx.y * 128, bn = blockIdx.x * 128;
    const int koff = (MODE == 2) ? blockIdx.z * K : 0;

    float acc[2][8][4];
#pragma unroll
    for (int mi = 0; mi < 2; mi++)
#pragma unroll
        for (int ni = 0; ni < 8; ni++)
#pragma unroll
            for (int e = 0; e < 4; e++) acc[mi][ni][e] = 0.f;

    const __nv_bfloat16* ag = A + (size_t)bm * Kld + koff;
    const __nv_bfloat16* bg = Bw + bn + (size_t)koff * N;

    auto issue = [&](int s, int k0) {
        unsigned sa = sbase + (unsigned)s * STG_B;
        unsigned sb = sa + ASTG;
#pragma unroll
        for (int i = 0; i < 4; i++) {               // A: 128 rows x 8 chunks
            int idx = tid + i * 256;
            int r = idx >> 3, c = idx & 7;
            cpasync16(sa + r * 128 + ((c ^ (r & 7)) << 4),
                      ag + (size_t)r * Kld + k0 + c * 8);
        }
#pragma unroll
        for (int i = 0; i < 4; i++) {               // B: 64 rows x 16 chunks
            int idx = tid + i * 256;
            int r = idx >> 4, c = idx & 15;
            cpasync16(sb + r * 256 + ((c ^ (r & 7)) << 4),
                      bg + (size_t)(k0 + r) * N + c * 8);
        }
    };

    const int nk = K >> 6;
    issue(0, 0);
    asm volatile("cp.async.commit_group;" ::: "memory");
    issue(1, 64);
    asm volatile("cp.async.commit_group;" ::: "memory");

    const unsigned aoff = (unsigned)((wm * 32 + (lane & 15)) * 128);
    const unsigned asel = (lane >> 4) & 1;
    const unsigned axor = lane & 7;
    const unsigned boff = (unsigned)((((lane & 7) + ((lane >> 3) & 1) * 8)) * 256);
    const unsigned bsel = (lane >> 4) & 1;

    for (int kt = 0; kt < nk; kt++) {
        asm volatile("cp.async.wait_group 1;" ::: "memory");
        __syncthreads();
        if (kt + 2 < nk) issue((kt + 2) % 3, (kt + 2) << 6);
        asm volatile("cp.async.commit_group;" ::: "memory");

        unsigned sa = sbase + (unsigned)(kt % 3) * STG_B;
        unsigned sb = sa + ASTG;
#pragma unroll
        for (int kk = 0; kk < 4; kk++) {
            unsigned a[2][4];
#pragma unroll
            for (int mi = 0; mi < 2; mi++)
                ldsm_x4(a[mi][0], a[mi][1], a[mi][2], a[mi][3],
                        sa + aoff + mi * 2048 + ((((unsigned)(kk * 2) + asel) ^ axor) << 4));
            unsigned b[8][2];
#pragma unroll
            for (int n2 = 0; n2 < 4; n2++) {
                unsigned nch = (unsigned)(wn * 8 + n2 * 2) + bsel;
                ldsm_x4t(b[2 * n2][0], b[2 * n2][1], b[2 * n2 + 1][0], b[2 * n2 + 1][1],
                         sb + kk * 4096 + boff + ((nch ^ axor) << 4));
            }
#pragma unroll
            for (int mi = 0; mi < 2; mi++)
#pragma unroll
                for (int ni = 0; ni < 8; ni++)
                    mma_bf16(acc[mi][ni], a[mi], b[ni]);
        }
    }

    const int r0base = bm + wm * 32 + (lane >> 2);
    const int colbase = bn + wn * 64 + (lane & 3) * 2;
    if (MODE == 0) {
        __nv_bfloat16* C = (__nv_bfloat16*)Cv;
#pragma unroll
        for (int mi = 0; mi < 2; mi++)
#pragma unroll
            for (int ni = 0; ni < 8; ni++) {
                int r0 = r0base + mi * 16, col = colbase + ni * 8;
                float2 bb = *reinterpret_cast<const float2*>(bias + col);
                *reinterpret_cast<unsigned*>(C + (size_t)r0 * N + col) =
                    pack_bf2(acc[mi][ni][0] + bb.x, acc[mi][ni][1] + bb.y);
                *reinterpret_cast<unsigned*>(C + (size_t)(r0 + 8) * N + col) =
                    pack_bf2(acc[mi][ni][2] + bb.x, acc[mi][ni][3] + bb.y);
            }
    } else if (MODE == 1) {
        float* C = (float*)Cv;
#pragma unroll
        for (int mi = 0; mi < 2; mi++)
#pragma unroll
            for (int ni = 0; ni < 8; ni++) {
                int r0 = r0base + mi * 16, col = colbase + ni * 8;
                float2 bb = *reinterpret_cast<const float2*>(bias + col);
                float2 ra = *reinterpret_cast<const float2*>(resid + (size_t)r0 * N + col);
                float2 rb = *reinterpret_cast<const float2*>(resid + (size_t)(r0 + 8) * N + col);
                float2 v0, v1;
                v0.x = acc[mi][ni][0] + bb.x + ra.x;
                v0.y = acc[mi][ni][1] + bb.y + ra.y;
                v1.x = acc[mi][ni][2] + bb.x + rb.x;
                v1.y = acc[mi][ni][3] + bb.y + rb.y;
                *reinterpret_cast<float2*>(C + (size_t)r0 * N + col) = v0;
                *reinterpret_cast<float2*>(C + (size_t)(r0 + 8) * N + col) = v1;
            }
    } else {
        float* C = (float*)Cv + (size_t)blockIdx.z * gridDim.y * 128 * N;
#pragma unroll
        for (int mi = 0; mi < 2; mi++)
#pragma unroll
            for (int ni = 0; ni < 8; ni++) {
                int r0 = r0base + mi * 16, col = colbase + ni * 8;
                float2 v0 = {acc[mi][ni][0], acc[mi][ni][1]};
                float2 v1 = {acc[mi][ni][2], acc[mi][ni][3]};
                *reinterpret_cast<float2*>(C + (size_t)r0 * N + col) = v0;
                *reinterpret_cast<float2*>(C + (size_t)(r0 + 8) * N + col) = v1;
            }
    }
}

// ---------------------------------------------------------------------------
// Launch. Order: prep(1), wcomb-splitk(2), wred(3), ln(4), adj(5), proj(6),
// ew(7), down(8).
// ---------------------------------------------------------------------------
extern "C" void kernel_launch(void* const* d_in, const int* in_sizes, int n_in,
                              void* d_out, int out_size) {
    const float* x      = (const float*)d_in[0];
    const float* ln1g   = (const float*)d_in[1];
    const float* ln1b   = (const float*)d_in[2];
    const float* W_up   = (const float*)d_in[3];
    const float* b_up   = (const float*)d_in[4];
    const float* W_adj  = (const float*)d_in[5];
    const float* b_adj  = (const float*)d_in[6];
    const float* W_q = (const float*)d_in[7];   const float* b_q = (const float*)d_in[8];
    const float* W_k = (const float*)d_in[9];   const float* b_k = (const float*)d_in[10];
    const float* W_v = (const float*)d_in[11];  const float* b_v = (const float*)d_in[12];
    const float* W_i = (const float*)d_in[13];  const float* b_i = (const float*)d_in[14];
    const float* W_f = (const float*)d_in[15];  const float* b_f = (const float*)d_in[16];
    const float* W_o = (const float*)d_in[17];  const float* b_o = (const float*)d_in[18];
    const float* ln2g   = (const float*)d_in[19];
    const float* ln2b   = (const float*)d_in[20];
    const float* W_down = (const float*)d_in[21];
    const float* b_down = (const float*)d_in[22];
    float* out = (float*)d_out;

    void* p;
    cudaGetSymbolAddress(&p, g_act); __nv_bfloat16* act = (__nv_bfloat16*)p;
    cudaGetSymbolAddress(&p, g_w);   __nv_bfloat16* w   = (__nv_bfloat16*)p;
    cudaGetSymbolAddress(&p, g_bcat);  float* bcat  = (float*)p;
    cudaGetSymbolAddress(&p, g_bcomb); float* bcomb = (float*)p;

    __nv_bfloat16* xn   = act;                // reused as y after adj-GEMM
    float*         wpart = (float*)(act + 1 * SZB);   // 8 x 1M fp32 partials
    __nv_bfloat16* adj  = act + 3 * SZB;
    __nv_bfloat16* proj = act + 4 * SZB;      // [N, 5120]
    __nv_bfloat16* y    = xn;

    __nv_bfloat16* w_up   = w;                // [1024,2048]
    __nv_bfloat16* w_adj  = w + 2 * M1;       // [2048,1024]
    __nv_bfloat16* w_cat  = w + 4 * M1;       // [1024,5120]
    __nv_bfloat16* w_down = w + 9 * M1;       // [1024,1024]
    __nv_bfloat16* w_comb = w + 10 * M1;      // [1024,1024]

    cudaFuncSetAttribute((const void*)gemm_bf16<0>,
                         cudaFuncAttributeMaxDynamicSharedMemorySize, GSMEM);
    cudaFuncSetAttribute((const void*)gemm_bf16<1>,
                         cudaFuncAttributeMaxDynamicSharedMemorySize, GSMEM);
    cudaFuncSetAttribute((const void*)gemm_bf16<2>,
                         cudaFuncAttributeMaxDynamicSharedMemorySize, GSMEM);

    // 1) all weight prep (incl. bcomb) in one launch
    prep_k<<<(R_BC + 255) / 256, 256>>>(W_up, W_adj, W_down,
                                        W_q, W_k, W_v, W_i, W_f, W_o,
                                        b_q, b_k, b_v, b_i, b_f, b_o,
                                        b_up, b_adj, w, bcat, bcomb);
    // 2) W_comb partials: split-K=8 over K=2048 (slices of 256)
    gemm_bf16<2><<<dim3(8, 8, 8), 256, GSMEM>>>(w_up, w_adj, nullptr, nullptr,
                                                wpart, 1024, 256, 2048);
    // 3) reduce partials -> w_comb (bf16)
    wred_k<<<1024, 256>>>(wpart, w_comb);
    // 4) LN1
    ln_kernel<<<NROWS, 256>>>(x, ln1g, ln1b, xn);
    // 5) adj = xn @ W_comb + b_comb   [N,1024]@[1024,1024]
    gemm_bf16<0><<<dim3(8, 128), 256, GSMEM>>>(xn, w_comb, bcomb, nullptr,
                                               adj, 1024, 1024, 1024);
    // 6) proj = adj @ W_cat + b_cat   [N,1024]@[1024,5120]
    gemm_bf16<0><<<dim3(40, 128), 256, GSMEM>>>(adj, w_cat, bcat, nullptr,
                                                proj, 5120, 1024, 1024);
    // 7) gates + LN2*sigmoid(adj)
    ew_kernel<<<NROWS, 256>>>(proj, adj, ln2g, ln2b, y);
    // 8) out = y @ W_down + b_down + x  (fp32)
    gemm_bf16<1><<<dim3(8, 128), 256, GSMEM>>>(y, w_down, b_down, x, out,
                                               1024, 1024, 1024);
}

// round 13
// speedup vs baseline: 1.1141x; 1.0270x over previous
#include <cuda_runtime.h>
#include <cuda_bf16.h>

// ---------------------------------------------------------------------------
// mLSTM block, GB300 sm_103a. Round 13:
//  - pipeline as round 12 (up/adj fused, f/i fused proj N=5120, prep+bcomb,
//    wcomb split-K=8 + reduce)
//  - GEMM mainloop: explicit fragment double-buffering within the 128-reg
//    cap (acc 64 + frags 48 + addr ~ 120 regs), warp tile 32x64 unchanged,
//    CTA 128x128x64, 256 thr, 3-stage cp.async, 2 CTAs/SM, XOR swizzle.
// ---------------------------------------------------------------------------

#define NROWS 16384
#define SZB (16384ull * 1024ull)
#define M1  (1024ull * 1024ull)

__device__ __align__(16) __nv_bfloat16 g_act[10ull * SZB];
__device__ __align__(16) __nv_bfloat16 g_w[11ull * M1];
__device__ __align__(16) float g_bcat[5120];
__device__ __align__(16) float g_bcomb[1024];

__device__ __forceinline__ unsigned pack_bf2(float a, float b) {
    __nv_bfloat162 h = __floats2bfloat162_rn(a, b);
    return *reinterpret_cast<unsigned*>(&h);
}
__device__ __forceinline__ float4 ld_bf4(const __nv_bfloat16* p) {
    uint2 u = *reinterpret_cast<const uint2*>(p);
    __nv_bfloat162 a = *reinterpret_cast<__nv_bfloat162*>(&u.x);
    __nv_bfloat162 b = *reinterpret_cast<__nv_bfloat162*>(&u.y);
    float4 r;
    r.x = __bfloat162float(a.x); r.y = __bfloat162float(a.y);
    r.z = __bfloat162float(b.x); r.w = __bfloat162float(b.y);
    return r;
}
__device__ __forceinline__ void cpasync16(unsigned dst, const void* src) {
    asm volatile("cp.async.cg.shared.global [%0], [%1], 16;" :: "r"(dst), "l"(src));
}
__device__ __forceinline__ void ldsm_x4(unsigned& r0, unsigned& r1, unsigned& r2,
                                        unsigned& r3, unsigned a) {
    asm volatile("ldmatrix.sync.aligned.m8n8.x4.shared.b16 {%0,%1,%2,%3}, [%4];"
                 : "=r"(r0), "=r"(r1), "=r"(r2), "=r"(r3) : "r"(a));
}
__device__ __forceinline__ void ldsm_x4t(unsigned& r0, unsigned& r1, unsigned& r2,
                                         unsigned& r3, unsigned a) {
    asm volatile("ldmatrix.sync.aligned.m8n8.x4.trans.shared.b16 {%0,%1,%2,%3}, [%4];"
                 : "=r"(r0), "=r"(r1), "=r"(r2), "=r"(r3) : "r"(a));
}
__device__ __forceinline__ void mma_bf16(float* c, const unsigned* a, const unsigned* b) {
    asm volatile("mma.sync.aligned.m16n8k16.row.col.f32.bf16.bf16.f32 "
                 "{%0,%1,%2,%3}, {%4,%5,%6,%7}, {%8,%9}, {%0,%1,%2,%3};"
                 : "+f"(c[0]), "+f"(c[1]), "+f"(c[2]), "+f"(c[3])
                 : "r"(a[0]), "r"(a[1]), "r"(a[2]), "r"(a[3]), "r"(b[0]), "r"(b[1]));
}

// ---------------------------------------------------------------------------
// Single prep kernel (unchanged).
// ---------------------------------------------------------------------------
#define R_A   524288
#define R_B   1048576
#define R_D   1310720
#define R_P   2621440
#define R_BI  2622720
#define R_BC  2623744

__global__ void prep_k(const float* __restrict__ W_up, const float* __restrict__ W_adj,
                       const float* __restrict__ W_down,
                       const float* __restrict__ Wq, const float* __restrict__ Wk,
                       const float* __restrict__ Wv, const float* __restrict__ Wi,
                       const float* __restrict__ Wf, const float* __restrict__ Wo,
                       const float* __restrict__ bq, const float* __restrict__ bk,
                       const float* __restrict__ bv, const float* __restrict__ bi,
                       const float* __restrict__ bf, const float* __restrict__ bo,
                       const float* __restrict__ b_up, const float* __restrict__ b_adj,
                       __nv_bfloat16* __restrict__ w, float* __restrict__ bcat,
                       float* __restrict__ bcomb) {
    int i = blockIdx.x * blockDim.x + threadIdx.x;
    if (i >= R_BC) return;
    if (i < R_D) {
        const float* src; __nv_bfloat16* dst; int off;
        if (i < R_A)      { src = W_up;   dst = w;          off = i; }
        else if (i < R_B) { src = W_adj;  dst = w + 2 * M1; off = i - R_A; }
        else              { src = W_down; dst = w + 9 * M1; off = i - R_B; }
        float4 v = reinterpret_cast<const float4*>(src)[off];
        uint2 u;
        u.x = pack_bf2(v.x, v.y); u.y = pack_bf2(v.z, v.w);
        reinterpret_cast<uint2*>(dst)[off] = u;
    } else if (i < R_P) {
        int li = i - R_D;
        int j = li >> 18, off = li & 262143;
        int k = off >> 8, c = off & 255;
        float4 v;
        if (j == 0)      v = reinterpret_cast<const float4*>(Wq)[off];
        else if (j == 1) {
            v = reinterpret_cast<const float4*>(Wk)[off];
            v.x *= 0.125f; v.y *= 0.125f; v.z *= 0.125f; v.w *= 0.125f;
        } else if (j == 2) v = reinterpret_cast<const float4*>(Wv)[off];
        else if (j == 3) {
            float4 a = reinterpret_cast<const float4*>(Wf)[off];
            float4 b = reinterpret_cast<const float4*>(Wi)[off];
            v.x = a.x - b.x; v.y = a.y - b.y; v.z = a.z - b.z; v.w = a.w - b.w;
        } else            v = reinterpret_cast<const float4*>(Wo)[off];
        uint2 u;
        u.x = pack_bf2(v.x, v.y); u.y = pack_bf2(v.z, v.w);
        *reinterpret_cast<uint2*>(w + 4 * M1 + (size_t)k * 5120 + (size_t)j * 1024 + c * 4) = u;
    } else if (i < R_BI) {
        int li = i - R_P;
        int j = li >> 8, off = li & 255;
        float4 v;
        if (j == 0)      v = reinterpret_cast<const float4*>(bq)[off];
        else if (j == 1) {
            v = reinterpret_cast<const float4*>(bk)[off];
            v.x *= 0.125f; v.y *= 0.125f; v.z *= 0.125f; v.w *= 0.125f;
        } else if (j == 2) v = reinterpret_cast<const float4*>(bv)[off];
        else if (j == 3) {
            float4 a = reinterpret_cast<const float4*>(bf)[off];
            float4 b = reinterpret_cast<const float4*>(bi)[off];
            v.x = a.x - b.x; v.y = a.y - b.y; v.z = a.z - b.z; v.w = a.w - b.w;
        } else            v = reinterpret_cast<const float4*>(bo)[off];
        reinterpret_cast<float4*>(bcat + (size_t)j * 1024)[off] = v;
    } else {
        int j = i - R_BI;
        float s = 0.f;
        for (int k = 0; k < 2048; k++) s += b_up[k] * W_adj[(size_t)k * 1024 + j];
        bcomb[j] = s + b_adj[j];
    }
}

// Reduce 8 fp32 split-K partials [8 x 1M] -> bf16 [1M]. float4 granular.
__global__ void wred_k(const float* __restrict__ part, __nv_bfloat16* __restrict__ out) {
    int i = blockIdx.x * blockDim.x + threadIdx.x;
    if (i >= 262144) return;
    float4 s = reinterpret_cast<const float4*>(part)[i];
#pragma unroll
    for (int p = 1; p < 8; p++) {
        float4 v = reinterpret_cast<const float4*>(part + (size_t)p * M1)[i];
        s.x += v.x; s.y += v.y; s.z += v.z; s.w += v.w;
    }
    uint2 u;
    u.x = pack_bf2(s.x, s.y); u.y = pack_bf2(s.z, s.w);
    reinterpret_cast<uint2*>(out)[i] = u;
}

// ---------------------------------------------------------------------------
// Block reduce (sum + sumsq) over 256 threads.
// ---------------------------------------------------------------------------
__device__ __forceinline__ void block_reduce2(float& s, float& ss, float* red) {
#pragma unroll
    for (int o = 16; o > 0; o >>= 1) {
        s  += __shfl_xor_sync(0xffffffffu, s,  o);
        ss += __shfl_xor_sync(0xffffffffu, ss, o);
    }
    int w = threadIdx.x >> 5;
    if ((threadIdx.x & 31) == 0) { red[w] = s; red[8 + w] = ss; }
    __syncthreads();
    s = 0.f; ss = 0.f;
#pragma unroll
    for (int i = 0; i < 8; i++) { s += red[i]; ss += red[8 + i]; }
}

// ---------------------------------------------------------------------------
// LN1: fp32 in, bf16 out. One block / row.
// ---------------------------------------------------------------------------
__global__ void ln_kernel(const float* __restrict__ x, const float* __restrict__ g,
                          const float* __restrict__ b, __nv_bfloat16* __restrict__ o) {
    __shared__ float red[16];
    int tid = threadIdx.x;
    size_t base = (size_t)blockIdx.x * 1024 + (size_t)tid * 4;
    float4 v = *reinterpret_cast<const float4*>(x + base);
    float s  = v.x + v.y + v.z + v.w;
    float ss = v.x*v.x + v.y*v.y + v.z*v.z + v.w*v.w;
    block_reduce2(s, ss, red);
    float mean = s * (1.f / 1024.f);
    float var  = ss * (1.f / 1024.f) - mean * mean;
    float rs = rsqrtf(var + 1e-3f);
    float4 gg = *reinterpret_cast<const float4*>(g + tid * 4);
    float4 bb = *reinterpret_cast<const float4*>(b + tid * 4);
    uint2 u;
    u.x = pack_bf2((v.x - mean) * rs * gg.x + bb.x, (v.y - mean) * rs * gg.y + bb.y);
    u.y = pack_bf2((v.z - mean) * rs * gg.z + bb.z, (v.w - mean) * rs * gg.w + bb.w);
    *reinterpret_cast<uint2*>(o + base) = u;
}

// ---------------------------------------------------------------------------
// Elementwise mLSTM + LN2 * sigmoid(adj). bf16 in/out. One block / row.
// proj rows 5120 wide: [q | k(scaled) | v | d=(f-i) | o].
// ---------------------------------------------------------------------------
__global__ void ew_kernel(const __nv_bfloat16* __restrict__ proj,
                          const __nv_bfloat16* __restrict__ adj,
                          const float* __restrict__ g2, const float* __restrict__ b2,
                          __nv_bfloat16* __restrict__ y) {
    __shared__ float red[16];
    int tid = threadIdx.x;
    size_t base5 = (size_t)blockIdx.x * 5120 + (size_t)tid * 4;
    size_t base  = (size_t)blockIdx.x * 1024 + (size_t)tid * 4;
    float4 q4 = ld_bf4(proj + base5);
    float4 k4 = ld_bf4(proj + base5 + 1024);
    float4 v4 = ld_bf4(proj + base5 + 2048);
    float4 d4 = ld_bf4(proj + base5 + 3072);
    float4 o4 = ld_bf4(proj + base5 + 4096);
    float qq[4] = {q4.x, q4.y, q4.z, q4.w};
    float kk[4] = {k4.x, k4.y, k4.z, k4.w};
    float vv[4] = {v4.x, v4.y, v4.z, v4.w};
    float dd[4] = {d4.x, d4.y, d4.z, d4.w};
    float oo[4] = {o4.x, o4.y, o4.z, o4.w};
    float h[4], s = 0.f, ss = 0.f;
#pragma unroll
    for (int e = 0; e < 4; e++) {
        float sig_o = 1.f / (1.f + __expf(-oo[e]));
        float fg = __expf(fminf(0.f, dd[e]));
        float u  = kk[e] * qq[e];
        float den = fmaxf(fabsf(u), 1.f);
        float hh = sig_o * fg * vv[e] * u / den;
        h[e] = hh; s += hh; ss += hh * hh;
    }
    block_reduce2(s, ss, red);
    float mean = s * (1.f / 1024.f);
    float var  = ss * (1.f / 1024.f) - mean * mean;
    float rs = rsqrtf(var + 1e-3f);
    float4 g4 = *reinterpret_cast<const float4*>(g2 + tid * 4);
    float4 bb4 = *reinterpret_cast<const float4*>(b2 + tid * 4);
    float4 a4 = ld_bf4(adj + base);
    float ga[4] = {g4.x, g4.y, g4.z, g4.w};
    float ba[4] = {bb4.x, bb4.y, bb4.z, bb4.w};
    float aa[4] = {a4.x, a4.y, a4.z, a4.w};
    float out[4];
#pragma unroll
    for (int e = 0; e < 4; e++) {
        float sig_a = 1.f / (1.f + __expf(-aa[e]));
        out[e] = ((h[e] - mean) * rs * ga[e] + ba[e]) * sig_a;
    }
    uint2 u;
    u.x = pack_bf2(out[0], out[1]); u.y = pack_bf2(out[2], out[3]);
    *reinterpret_cast<uint2*>(y + base) = u;
}

// ---------------------------------------------------------------------------
// bf16 GEMM: C = A[M,Kld sliced] @ B[K,N] (+bias / +resid per MODE).
// MODE 0: bf16 out + bias.  MODE 1: fp32 out + bias + resid.
// MODE 2: fp32 partial (split-K over blockIdx.z; no bias).
// CTA 128x128x64, 256 threads, warp tile 32x64 (4M x 2N warps),
// 3-stage cp.async (96KB -> 2 CTAs/SM), XOR swizzle, 1 barrier / k-chunk.
// NEW: explicit fragment double-buffer across kk (fits 128-reg budget:
// acc 64 + frags 48 + addressing).
// M%128==0, N%128==0, K%64==0.
// ---------------------------------------------------------------------------
#define STG_B 32768u       // A 16KB + B 16KB
#define ASTG  16384u
#define GSMEM (3u * STG_B)

template<int MODE>
__global__ __launch_bounds__(256, 2) void gemm_bf16(
    const __nv_bfloat16* __restrict__ A, const __nv_bfloat16* __restrict__ Bw,
    const float* __restrict__ bias, const float* __restrict__ resid,
    void* __restrict__ Cv, int N, int K, int Kld) {
    extern __shared__ char smc[];
    unsigned sbase = (unsigned)__cvta_generic_to_shared(smc);
    const int tid = threadIdx.x, lane = tid & 31, wid = tid >> 5;
    const int wm = wid & 3, wn = wid >> 2;          // 4 M-warps x 2 N-warps
    const int bm = blockIdx.y * 128, bn = blockIdx.x * 128;
    const int koff = (MODE == 2) ? blockIdx.z * K : 0;

    float acc[2][8][4];
#pragma unroll
    for (int mi = 0; mi < 2; mi++)
#pragma unroll
        for (int ni = 0; ni < 8; ni++)
#pragma unroll
            for (int e = 0; e < 4; e++) acc[mi][ni][e] = 0.f;

    const __nv_bfloat16* ag = A + (size_t)bm * Kld + koff;
    const __nv_bfloat16* bg = Bw + bn + (size_t)koff * N;

    auto issue = [&](int s, int k0) {
        unsigned sa = sbase + (unsigned)s * STG_B;
        unsigned sb = sa + ASTG;
#pragma unroll
        for (int i = 0; i < 4; i++) {               // A: 128 rows x 8 chunks
            int idx = tid + i * 256;
            int r = idx >> 3, c = idx & 7;
            cpasync16(sa + r * 128 + ((c ^ (r & 7)) << 4),
                      ag + (size_t)r * Kld + k0 + c * 8);
        }
#pragma unroll
        for (int i = 0; i < 4; i++) {               // B: 64 rows x 16 chunks
            int idx = tid + i * 256;
            int r = idx >> 4, c = idx & 15;
            cpasync16(sb + r * 256 + ((c ^ (r & 7)) << 4),
                      bg + (size_t)(k0 + r) * N + c * 8);
        }
    };

    const int nk = K >> 6;
    issue(0, 0);
    asm volatile("cp.async.commit_group;" ::: "memory");
    issue(1, 64);
    asm volatile("cp.async.commit_group;" ::: "memory");

    const unsigned aoff = (unsigned)((wm * 32 + (lane & 15)) * 128);
    const unsigned asel = (lane >> 4) & 1;
    const unsigned axor = lane & 7;
    const unsigned boff = (unsigned)((((lane & 7) + ((lane >> 3) & 1) * 8)) * 256);
    const unsigned bsel = (lane >> 4) & 1;

    unsigned af[2][2][4], bf[2][8][2];
    auto lfrag = [&](int buf, unsigned sa, unsigned sb, int kk) {
#pragma unroll
        for (int mi = 0; mi < 2; mi++)
            ldsm_x4(af[buf][mi][0], af[buf][mi][1], af[buf][mi][2], af[buf][mi][3],
                    sa + aoff + mi * 2048 + ((((unsigned)(kk * 2) + asel) ^ axor) << 4));
#pragma unroll
        for (int n2 = 0; n2 < 4; n2++) {
            unsigned nch = (unsigned)(wn * 8 + n2 * 2) + bsel;
            ldsm_x4t(bf[buf][2 * n2][0], bf[buf][2 * n2][1],
                     bf[buf][2 * n2 + 1][0], bf[buf][2 * n2 + 1][1],
                     sb + kk * 4096 + boff + ((nch ^ axor) << 4));
        }
    };

    for (int kt = 0; kt < nk; kt++) {
        asm volatile("cp.async.wait_group 1;" ::: "memory");
        __syncthreads();
        if (kt + 2 < nk) issue((kt + 2) % 3, (kt + 2) << 6);
        asm volatile("cp.async.commit_group;" ::: "memory");

        unsigned sa = sbase + (unsigned)(kt % 3) * STG_B;
        unsigned sb = sa + ASTG;
        lfrag(0, sa, sb, 0);
#pragma unroll
        for (int kk = 0; kk < 4; kk++) {
            int cur = kk & 1;
            if (kk < 3) lfrag(cur ^ 1, sa, sb, kk + 1);
#pragma unroll
            for (int mi = 0; mi < 2; mi++)
#pragma unroll
                for (int ni = 0; ni < 8; ni++)
                    mma_bf16(acc[mi][ni], af[cur][mi], bf[cur][ni]);
        }
    }

    const int r0base = bm + wm * 32 + (lane >> 2);
    const int colbase = bn + wn * 64 + (lane & 3) * 2;
    if (MODE == 0) {
        __nv_bfloat16* C = (__nv_bfloat16*)Cv;
#pragma unroll
        for (int mi = 0; mi < 2; mi++)
#pragma unroll
            for (int ni = 0; ni < 8; ni++) {
                int r0 = r0base + mi * 16, col = colbase + ni * 8;
                float2 bb = *reinterpret_cast<const float2*>(bias + col);
                *reinterpret_cast<unsigned*>(C + (size_t)r0 * N + col) =
                    pack_bf2(acc[mi][ni][0] + bb.x, acc[mi][ni][1] + bb.y);
                *reinterpret_cast<unsigned*>(C + (size_t)(r0 + 8) * N + col) =
                    pack_bf2(acc[mi][ni][2] + bb.x, acc[mi][ni][3] + bb.y);
            }
    } else if (MODE == 1) {
        float* C = (float*)Cv;
#pragma unroll
        for (int mi = 0; mi < 2; mi++)
#pragma unroll
            for (int ni = 0; ni < 8; ni++) {
                int r0 = r0base + mi * 16, col = colbase + ni * 8;
                float2 bb = *reinterpret_cast<const float2*>(bias + col);
                float2 ra = *reinterpret_cast<const float2*>(resid + (size_t)r0 * N + col);
                float2 rb = *reinterpret_cast<const float2*>(resid + (size_t)(r0 + 8) * N + col);
                float2 v0, v1;
                v0.x = acc[mi][ni][0] + bb.x + ra.x;
                v0.y = acc[mi][ni][1] + bb.y + ra.y;
                v1.x = acc[mi][ni][2] + bb.x + rb.x;
                v1.y = acc[mi][ni][3] + bb.y + rb.y;
                *reinterpret_cast<float2*>(C + (size_t)r0 * N + col) = v0;
                *reinterpret_cast<float2*>(C + (size_t)(r0 + 8) * N + col) = v1;
            }
    } else {
        float* C = (float*)Cv + (size_t)blockIdx.z * gridDim.y * 128 * N;
#pragma unroll
        for (int mi = 0; mi < 2; mi++)
#pragma unroll
            for (int ni = 0; ni < 8; ni++) {
                int r0 = r0base + mi * 16, col = colbase + ni * 8;
                float2 v0 = {acc[mi][ni][0], acc[mi][ni][1]};
                float2 v1 = {acc[mi][ni][2], acc[mi][ni][3]};
                *reinterpret_cast<float2*>(C + (size_t)r0 * N + col) = v0;
                *reinterpret_cast<float2*>(C + (size_t)(r0 + 8) * N + col) = v1;
            }
    }
}

// ---------------------------------------------------------------------------
// Launch. Order: prep(1), wcomb-splitk(2), wred(3), ln(4), adj(5), proj(6),
// ew(7), down(8).
// ---------------------------------------------------------------------------
extern "C" void kernel_launch(void* const* d_in, const int* in_sizes, int n_in,
                              void* d_out, int out_size) {
    const float* x      = (const float*)d_in[0];
    const float* ln1g   = (const float*)d_in[1];
    const float* ln1b   = (const float*)d_in[2];
    const float* W_up   = (const float*)d_in[3];
    const float* b_up   = (const float*)d_in[4];
    const float* W_adj  = (const float*)d_in[5];
    const float* b_adj  = (const float*)d_in[6];
    const float* W_q = (const float*)d_in[7];   const float* b_q = (const float*)d_in[8];
    const float* W_k = (const float*)d_in[9];   const float* b_k = (const float*)d_in[10];
    const float* W_v = (const float*)d_in[11];  const float* b_v = (const float*)d_in[12];
    const float* W_i = (const float*)d_in[13];  const float* b_i = (const float*)d_in[14];
    const float* W_f = (const float*)d_in[15];  const float* b_f = (const float*)d_in[16];
    const float* W_o = (const float*)d_in[17];  const float* b_o = (const float*)d_in[18];
    const float* ln2g   = (const float*)d_in[19];
    const float* ln2b   = (const float*)d_in[20];
    const float* W_down = (const float*)d_in[21];
    const float* b_down = (const float*)d_in[22];
    float* out = (float*)d_out;

    void* p;
    cudaGetSymbolAddress(&p, g_act); __nv_bfloat16* act = (__nv_bfloat16*)p;
    cudaGetSymbolAddress(&p, g_w);   __nv_bfloat16* w   = (__nv_bfloat16*)p;
    cudaGetSymbolAddress(&p, g_bcat);  float* bcat  = (float*)p;
    cudaGetSymbolAddress(&p, g_bcomb); float* bcomb = (float*)p;

    __nv_bfloat16* xn   = act;                // reused as y after adj-GEMM
    float*         wpart = (float*)(act + 1 * SZB);   // 8 x 1M fp32 partials
    __nv_bfloat16* adj  = act + 3 * SZB;
    __nv_bfloat16* proj = act + 4 * SZB;      // [N, 5120]
    __nv_bfloat16* y    = xn;

    __nv_bfloat16* w_up   = w;                // [1024,2048]
    __nv_bfloat16* w_adj  = w + 2 * M1;       // [2048,1024]
    __nv_bfloat16* w_cat  = w + 4 * M1;       // [1024,5120]
    __nv_bfloat16* w_down = w + 9 * M1;       // [1024,1024]
    __nv_bfloat16* w_comb = w + 10 * M1;      // [1024,1024]

    cudaFuncSetAttribute((const void*)gemm_bf16<0>,
                         cudaFuncAttributeMaxDynamicSharedMemorySize, GSMEM);
    cudaFuncSetAttribute((const void*)gemm_bf16<1>,
                         cudaFuncAttributeMaxDynamicSharedMemorySize, GSMEM);
    cudaFuncSetAttribute((const void*)gemm_bf16<2>,
                         cudaFuncAttributeMaxDynamicSharedMemorySize, GSMEM);

    // 1) all weight prep (incl. bcomb) in one launch
    prep_k<<<(R_BC + 255) / 256, 256>>>(W_up, W_adj, W_down,
                                        W_q, W_k, W_v, W_i, W_f, W_o,
                                        b_q, b_k, b_v, b_i, b_f, b_o,
                                        b_up, b_adj, w, bcat, bcomb);
    // 2) W_comb partials: split-K=8 over K=2048 (slices of 256)
    gemm_bf16<2><<<dim3(8, 8, 8), 256, GSMEM>>>(w_up, w_adj, nullptr, nullptr,
                                                wpart, 1024, 256, 2048);
    // 3) reduce partials -> w_comb (bf16)
    wred_k<<<1024, 256>>>(wpart, w_comb);
    // 4) LN1
    ln_kernel<<<NROWS, 256>>>(x, ln1g, ln1b, xn);
    // 5) adj = xn @ W_comb + b_comb   [N,1024]@[1024,1024]
    gemm_bf16<0><<<dim3(8, 128), 256, GSMEM>>>(xn, w_comb, bcomb, nullptr,
                                               adj, 1024, 1024, 1024);
    // 6) proj = adj @ W_cat + b_cat   [N,1024]@[1024,5120]
    gemm_bf16<0><<<dim3(40, 128), 256, GSMEM>>>(adj, w_cat, bcat, nullptr,
                                                proj, 5120, 1024, 1024);
    // 7) gates + LN2*sigmoid(adj)
    ew_kernel<<<NROWS, 256>>>(proj, adj, ln2g, ln2b, y);
    // 8) out = y @ W_down + b_down + x  (fp32)
    gemm_bf16<1><<<dim3(8, 128), 256, GSMEM>>>(y, w_down, b_down, x, out,
                                               1024, 1024, 1024);
}